// round 1
// baseline (speedup 1.0000x reference)
#include <cuda_runtime.h>
#include <cstdint>

// Problem constants for IdealLearner_90177133347004
#define S_LEN   4096
#define NTASKS  256
#define NALGOS  64

// Inter-kernel scalar-chain buffer: g[a][s] = sig_s(t_{s+1})
__device__ float g_buf[NALGOS * S_LEN];

__device__ __forceinline__ float ex2f(float x) {
    float y; asm("ex2.approx.f32 %0, %1;" : "=f"(y) : "f"(x)); return y;
}
__device__ __forceinline__ float rcpf(float x) {
    float y; asm("rcp.approx.f32 %0, %1;" : "=f"(y) : "f"(x)); return y;
}
// 2*sigmoid(z)-1 with z = r/d, computed as 2/(1+exp(-z)) - 1.
// Input pre-scaled: x2 = r * w2 where w2 = -log2(e)/d, so exp(-z) = ex2(x2).
__device__ __forceinline__ float sig_from_scaled(float x2) {
    float e  = ex2f(x2);
    float rc = rcpf(e + 1.0f);
    return fmaf(2.0f, rc, -1.0f);
}

// ---------------------------------------------------------------------------
// Producer: one warp per algo. Maintains full 256-wide res state (8 cols/lane,
// mirrored in smem) and runs the pipelined scalar chain g_s.
// ---------------------------------------------------------------------------
__global__ void __launch_bounds__(32, 1) idl_producer(
    const int*   __restrict__ lx,
    const float* __restrict__ tm,
    const float* __restrict__ diff,
    const float* __restrict__ effA,
    const float* __restrict__ memA,
    const float* __restrict__ boostA)
{
    __shared__ float r_sh[NTASKS];
    __shared__ float w2_sh[NTASKS];

    const int a    = blockIdx.x;
    const int lane = threadIdx.x;

    const float mem   = memA[a];
    const float eff   = effA[a];
    const float boost = boostA[a];

    const float NLOG2E = -1.4426950408889634f;
    #pragma unroll
    for (int c = lane; c < NTASKS; c += 32) {
        w2_sh[c] = NLOG2E / diff[c];
        r_sh[c]  = 0.0f;
    }
    __syncwarp();

    // res state: cols lane*8 + 0..7
    float r0 = 0.f, r1 = 0.f, r2 = 0.f, r3 = 0.f;
    float r4 = 0.f, r5 = 0.f, r6 = 0.f, r7 = 0.f;

    // t queue (depth 16), rows (depth 8), tm[t_s][t_{s+1}] scalars (depth 8)
    int tq[16];
    #pragma unroll
    for (int i = 0; i < 16; i++) tq[i] = lx[i];

    float4 ra[8], rb[8];
    #pragma unroll
    for (int i = 0; i < 8; i++) {
        const float4* rp = (const float4*)(tm + tq[i] * NTASKS + lane * 8);
        ra[i] = __ldg(rp);
        rb[i] = __ldg(rp + 1);
    }
    float tmcq[8];
    #pragma unroll
    for (int i = 0; i < 8; i++)
        tmcq[i] = __ldg(tm + tq[i] * NTASKS + tq[i + 1]);

    float g    = 0.0f;                         // g_{-1}
    float P2   = 0.0f;                         // r_{-1}(c_0)*mem*w2 = 0
    float TMW2 = tmcq[0] * w2_sh[tq[1]];       // tm[t0][t1]*w2[t1]

    float* gout = g_buf + a * S_LEN;

    for (int sb = 0; sb < S_LEN; sb += 16) {
        #pragma unroll
        for (int u = 0; u < 16; u++) {
            const int s = sb + u;

            // ---- critical scalar chain ----
            float k  = fmaf(boost, g, eff);
            float x2 = fmaf(TMW2, k, P2);
            g = sig_from_scaled(x2);
            if (lane == 0) gout[s] = g;

            // ---- vector res update (cols lane*8..+7) ----
            const float4 va = ra[u & 7];
            const float4 vb = rb[u & 7];
            r0 = fmaf(r0, mem, va.x * k);
            r1 = fmaf(r1, mem, va.y * k);
            r2 = fmaf(r2, mem, va.z * k);
            r3 = fmaf(r3, mem, va.w * k);
            r4 = fmaf(r4, mem, vb.x * k);
            r5 = fmaf(r5, mem, vb.y * k);
            r6 = fmaf(r6, mem, vb.z * k);
            r7 = fmaf(r7, mem, vb.w * k);

            // mirror to smem for next-step broadcast
            float4* rs = (float4*)(r_sh + lane * 8);
            rs[0] = make_float4(r0, r1, r2, r3);
            rs[1] = make_float4(r4, r5, r6, r7);
            __syncwarp();

            // ---- prepare next step's P2 / TMW2 (c_{s+1} = t_{s+2}) ----
            const int   cn  = tq[(u + 2) & 15];
            const float w2n = w2_sh[cn];
            P2   = r_sh[cn] * mem * w2n;
            TMW2 = tmcq[(u + 1) & 7] * w2n;

            // ---- prefetch step s+8 row + tm scalar; refill t queue ----
            const int t8 = tq[(u + 8) & 15];
            const int t9 = tq[(u + 9) & 15];
            const float4* rp = (const float4*)(tm + t8 * NTASKS + lane * 8);
            ra[u & 7] = __ldg(rp);
            rb[u & 7] = __ldg(rp + 1);
            tmcq[u & 7] = __ldg(tm + t8 * NTASKS + t9);

            const int nidx = s + 16;
            tq[u] = lx[nidx < S_LEN ? nidx : (S_LEN - 1)];
        }
    }
}

// ---------------------------------------------------------------------------
// Follower: 128 blocks (2 per algo, 128 cols each), one thread per (a, col).
// Recomputes the res chain (serial dep = 1 FFMA/step), sigmoids, and writes
// output coalesced along s via a smem transpose (16-step chunks).
// ---------------------------------------------------------------------------
__global__ void __launch_bounds__(128) idl_follower(
    const int*   __restrict__ lx,
    const float* __restrict__ tm,
    const float* __restrict__ diff,
    const float* __restrict__ effA,
    const float* __restrict__ memA,
    const float* __restrict__ boostA,
    float*       __restrict__ out)
{
    __shared__ float sbuf[128][17];

    const int b       = blockIdx.x;
    const int a       = b >> 1;
    const int colbase = (b & 1) * 128;
    const int tid     = threadIdx.x;
    const int col     = colbase + tid;
    const int lane    = tid & 31;
    const int w       = tid >> 5;

    const float mem   = memA[a];
    const float eff   = effA[a];
    const float boost = boostA[a];
    const float w2    = -1.4426950408889634f / diff[col];

    const float* gsrc = g_buf + a * S_LEN;

    float r = 0.0f;

    // zero column 0 of the output for this (a, col)
    const size_t obase = ((size_t)(a * NTASKS + col)) * (size_t)(S_LEN + 1);
    out[obase] = 0.0f;

    for (int chunk = 0; chunk < S_LEN / 16; chunk++) {
        const int s0 = chunk * 16;
        #pragma unroll
        for (int j = 0; j < 16; j++) {
            const int s = s0 + j;
            const int t = __ldg(lx + s);
            const float gp = (s == 0) ? 0.0f : __ldg(gsrc + s - 1);
            const float k  = fmaf(boost, gp, eff);
            const float tv = __ldg(tm + t * NTASKS + col);
            r = fmaf(r, mem, tv * k);
            sbuf[tid][j] = sig_from_scaled(r * w2);
        }
        __syncwarp();
        // coalesced write-out: each warp owns local cols [w*32, w*32+32)
        #pragma unroll
        for (int i = 0; i < 16; i++) {
            const int cc = (w << 5) + (i << 1) + (lane >> 4);
            const int j  = lane & 15;
            const float v = sbuf[cc][j];
            out[((size_t)(a * NTASKS + colbase + cc)) * (size_t)(S_LEN + 1)
                + 1 + s0 + j] = v;
        }
        __syncwarp();
    }
}

extern "C" void kernel_launch(void* const* d_in, const int* in_sizes, int n_in,
                              void* d_out, int out_size)
{
    (void)in_sizes; (void)n_in; (void)out_size;
    const int*   lx    = (const int*)  d_in[0];
    const float* tm    = (const float*)d_in[1];
    const float* diff  = (const float*)d_in[2];
    const float* eff   = (const float*)d_in[3];
    const float* mem   = (const float*)d_in[4];
    const float* boost = (const float*)d_in[5];
    float*       out   = (float*)d_out;

    idl_producer<<<NALGOS, 32>>>(lx, tm, diff, eff, mem, boost);
    idl_follower<<<NALGOS * 2, 128>>>(lx, tm, diff, eff, mem, boost, out);
}

// round 2
// speedup vs baseline: 1.4856x; 1.4856x over previous
#include <cuda_runtime.h>
#include <cstdint>

// Problem constants for IdealLearner_90177133347004
#define S_LEN   4096
#define NTASKS  256
#define NALGOS  64

// Inter-kernel buffer: k[a][s] = eff_a + boost_a * sig_{s-1}(t_s)
__device__ float k_buf[NALGOS * S_LEN];

__device__ __forceinline__ float ex2f(float x) {
    float y; asm("ex2.approx.f32 %0, %1;" : "=f"(y) : "f"(x)); return y;
}
__device__ __forceinline__ float rcpf(float x) {
    float y; asm("rcp.approx.f32 %0, %1;" : "=f"(y) : "f"(x)); return y;
}
__device__ __forceinline__ float tanhapx(float x) {
    float y; asm("tanh.approx.f32 %0, %1;" : "=f"(y) : "f"(x)); return y;
}
// exact: 2*sigmoid(z)-1 with x2 = r * (-log2e/d)
__device__ __forceinline__ float sig_from_scaled(float x2) {
    float e  = ex2f(x2);
    float rc = rcpf(e + 1.0f);
    return fmaf(2.0f, rc, -1.0f);
}

#define PACK64(u, lo, hi)  asm("mov.b64 %0, {%1, %2};" : "=l"(u) : "f"(lo), "f"(hi))
#define UNPACK64(lo, hi, u) asm("mov.b64 {%0, %1}, %2;" : "=f"(lo), "=f"(hi) : "l"(u))
#define MULX2(o, a, b) asm("mul.rn.f32x2 %0, %1, %2;" : "=l"(o) : "l"(a), "l"(b))
#define FMAX2(o, a, b, c) asm("fma.rn.f32x2 %0, %1, %2, %3;" : "=l"(o) : "l"(a), "l"(b), "l"(c))
#define LDG64(v, p) asm("ld.global.nc.b64 %0, [%1];" : "=l"(v) : "l"(p))

// ---------------------------------------------------------------------------
// Producer: one warp per algo. Maintains full 256-wide res state (8 cols/lane)
// and runs the pipelined scalar chain; cross-lane scalar via SEL tree + SHFL
// (no smem / syncwarp on the critical path). Writes k_s to k_buf.
// ---------------------------------------------------------------------------
__global__ void __launch_bounds__(32, 1) idl_producer(
    const int*   __restrict__ lx,
    const float* __restrict__ tm,
    const float* __restrict__ diff,
    const float* __restrict__ effA,
    const float* __restrict__ memA,
    const float* __restrict__ boostA)
{
    __shared__ float w2_sh[NTASKS];

    const int a    = blockIdx.x;
    const int lane = threadIdx.x;

    const float mem   = memA[a];
    const float eff   = effA[a];
    const float boost = boostA[a];

    const float NLOG2E = -1.4426950408889634f;
    #pragma unroll
    for (int c = lane; c < NTASKS; c += 32)
        w2_sh[c] = NLOG2E / diff[c];
    __syncwarp();

    // res state: cols lane*8 + 0..7
    float r0 = 0.f, r1 = 0.f, r2 = 0.f, r3 = 0.f;
    float r4 = 0.f, r5 = 0.f, r6 = 0.f, r7 = 0.f;

    int tq[16];
    #pragma unroll
    for (int i = 0; i < 16; i++) tq[i] = lx[i];

    float4 ra[8], rb[8];
    #pragma unroll
    for (int i = 0; i < 8; i++) {
        const float4* rp = (const float4*)(tm + tq[i] * NTASKS + lane * 8);
        ra[i] = __ldg(rp);
        rb[i] = __ldg(rp + 1);
    }
    float tmcq[8];
    #pragma unroll
    for (int i = 0; i < 8; i++)
        tmcq[i] = __ldg(tm + tq[i] * NTASKS + tq[i + 1]);

    float g    = 0.0f;
    float P2   = 0.0f;
    float TMW2 = tmcq[0] * w2_sh[tq[1]];

    float* kout = k_buf + a * S_LEN;

    for (int sb = 0; sb < S_LEN; sb += 16) {
        #pragma unroll
        for (int u = 0; u < 16; u++) {
            const int s = sb + u;

            // ---- critical scalar chain ----
            float k  = fmaf(boost, g, eff);
            float x2 = fmaf(TMW2, k, P2);
            g = sig_from_scaled(x2);
            if (lane == 0) kout[s] = k;

            // ---- vector res update (cols lane*8..+7) ----
            const float4 va = ra[u & 7];
            const float4 vb = rb[u & 7];
            r0 = fmaf(r0, mem, va.x * k);
            r1 = fmaf(r1, mem, va.y * k);
            r2 = fmaf(r2, mem, va.z * k);
            r3 = fmaf(r3, mem, va.w * k);
            r4 = fmaf(r4, mem, vb.x * k);
            r5 = fmaf(r5, mem, vb.y * k);
            r6 = fmaf(r6, mem, vb.z * k);
            r7 = fmaf(r7, mem, vb.w * k);

            // ---- cross-lane extract of r_s(t_{s+2}) via SEL tree + shfl ----
            const int cn   = tq[(u + 2) & 15];
            const float w2n = w2_sh[cn];
            const int ridx = cn & 7;
            float sA = (ridx & 1) ? r1 : r0;
            float sB = (ridx & 1) ? r3 : r2;
            float sC = (ridx & 1) ? r5 : r4;
            float sD = (ridx & 1) ? r7 : r6;
            float tA = (ridx & 2) ? sB : sA;
            float tB = (ridx & 2) ? sD : sC;
            float v  = (ridx & 4) ? tB : tA;
            float bc = __shfl_sync(0xffffffffu, v, cn >> 3);
            P2   = bc * (mem * w2n);
            TMW2 = tmcq[(u + 1) & 7] * w2n;

            // ---- prefetch step s+8 row + tm scalar; refill t queue ----
            const int t8 = tq[(u + 8) & 15];
            const int t9 = tq[(u + 9) & 15];
            const float4* rp = (const float4*)(tm + t8 * NTASKS + lane * 8);
            ra[u & 7] = __ldg(rp);
            rb[u & 7] = __ldg(rp + 1);
            tmcq[u & 7] = __ldg(tm + t8 * NTASKS + t9);

            const int nidx = s + 16;
            tq[u] = lx[nidx < S_LEN ? nidx : (S_LEN - 1)];
        }
    }
}

// ---------------------------------------------------------------------------
// Follower: 64 algos x 16 s-chunks = 1024 blocks, 128 threads, 2 cols/thread.
// Each chunk recomputes res with a 128-step warm-up (mem^128 < 1e-11), then
// emits tanh.approx sigmoids. Packed f32x2 recurrence, immediate-offset STGs.
// ---------------------------------------------------------------------------
#define F_CHUNK 256
#define F_WARM  128

__global__ void __launch_bounds__(128) idl_follower(
    const int*   __restrict__ lx,
    const float* __restrict__ tm,
    const float* __restrict__ diff,
    const float* __restrict__ memA,
    float*       __restrict__ out)
{
    const int blk   = blockIdx.x;
    const int a     = blk >> 4;
    const int chunk = blk & 15;
    const int tid   = threadIdx.x;
    const int c0    = 2 * tid;

    const float memv = memA[a];
    const float wh0  = 0.5f * rcpf(__ldg(diff + c0));
    const float wh1  = 0.5f * rcpf(__ldg(diff + c0 + 1));

    const float* kptr = k_buf + a * S_LEN;

    uint64_t rr = 0;                  // packed (r_c0, r_c1) = (0.f, 0.f)
    uint64_t memm; PACK64(memm, memv, memv);

    const int s_main  = chunk * F_CHUNK;
    const int s_start = (s_main >= F_WARM) ? (s_main - F_WARM) : 0;

    // warm-up (no sigmoid / no store)
    #pragma unroll 8
    for (int s = s_start; s < s_main; s++) {
        const int   t  = __ldg(lx + s);
        const float kv = __ldg(kptr + s);
        uint64_t kk;  PACK64(kk, kv, kv);
        uint64_t tv;  LDG64(tv, (const void*)(tm + t * NTASKS + c0));
        uint64_t pr;  MULX2(pr, tv, kk);
        FMAX2(rr, rr, memm, pr);
    }

    float* p0 = out + (size_t)(a * NTASKS + c0) * (size_t)(S_LEN + 1) + 1 + s_main;
    float* p1 = p0 + (S_LEN + 1);
    if (chunk == 0) { p0[-1] = 0.0f; p1[-1] = 0.0f; }

    #pragma unroll 16
    for (int j = 0; j < F_CHUNK; j++) {
        const int   s  = s_main + j;
        const int   t  = __ldg(lx + s);
        const float kv = __ldg(kptr + s);
        uint64_t kk;  PACK64(kk, kv, kv);
        uint64_t tv;  LDG64(tv, (const void*)(tm + t * NTASKS + c0));
        uint64_t pr;  MULX2(pr, tv, kk);
        FMAX2(rr, rr, memm, pr);
        float lo, hi; UNPACK64(lo, hi, rr);
        p0[j] = tanhapx(lo * wh0);
        p1[j] = tanhapx(hi * wh1);
    }
}

extern "C" void kernel_launch(void* const* d_in, const int* in_sizes, int n_in,
                              void* d_out, int out_size)
{
    (void)in_sizes; (void)n_in; (void)out_size;
    const int*   lx    = (const int*)  d_in[0];
    const float* tm    = (const float*)d_in[1];
    const float* diff  = (const float*)d_in[2];
    const float* eff   = (const float*)d_in[3];
    const float* mem   = (const float*)d_in[4];
    const float* boost = (const float*)d_in[5];
    float*       out   = (float*)d_out;

    idl_producer<<<NALGOS, 32>>>(lx, tm, diff, eff, mem, boost);
    idl_follower<<<NALGOS * 16, 128>>>(lx, tm, diff, mem, out);
}

// round 3
// speedup vs baseline: 2.0961x; 1.4109x over previous
#include <cuda_runtime.h>
#include <cstdint>

// Problem constants for IdealLearner_90177133347004
#define S_LEN   4096
#define NTASKS  256
#define NALGOS  64

// Inter-kernel buffer: k[a][s] = eff_a + boost_a * sig_{s-1}(t_s)
__device__ __align__(16) float k_buf[NALGOS * S_LEN];

__device__ __forceinline__ float rcpf(float x) {
    float y; asm("rcp.approx.f32 %0, %1;" : "=f"(y) : "f"(x)); return y;
}
__device__ __forceinline__ float tanhapx(float x) {
    float y; asm("tanh.approx.f32 %0, %1;" : "=f"(y) : "f"(x)); return y;
}

#define PACK64(u, lo, hi)   asm("mov.b64 %0, {%1, %2};" : "=l"(u) : "f"(lo), "f"(hi))
#define UNPACK64(lo, hi, u) asm("mov.b64 {%0, %1}, %2;" : "=f"(lo), "=f"(hi) : "l"(u))
#define MULX2(o, a, b)      asm("mul.rn.f32x2 %0, %1, %2;" : "=l"(o) : "l"(a), "l"(b))
#define FMAX2(o, a, b, c)   asm("fma.rn.f32x2 %0, %1, %2, %3;" : "=l"(o) : "l"(a), "l"(b), "l"(c))

// ---------------------------------------------------------------------------
// Producer: one warp per algo. Packed-f32x2 256-wide res state (8 cols/lane),
// tanh.approx scalar chain (24-cyc), SEL-tree + SHFL cross-lane extraction,
// 8-deep row prefetch. Emits k_s = eff + boost*g_{s-1} (float4 stores).
// ---------------------------------------------------------------------------
__global__ void __launch_bounds__(32, 1) idl_producer(
    const int*   __restrict__ lx,
    const float* __restrict__ tm,
    const float* __restrict__ diff,
    const float* __restrict__ effA,
    const float* __restrict__ memA,
    const float* __restrict__ boostA)
{
    __shared__ float2 wm_sh[NTASKS];   // {wh = 0.5/d, mem*wh}

    const int a    = blockIdx.x;
    const int lane = threadIdx.x;

    const float mem   = memA[a];
    const float eff   = effA[a];
    const float boost = boostA[a];

    #pragma unroll
    for (int c = lane; c < NTASKS; c += 32) {
        float wh = 0.5f * rcpf(diff[c]);
        wm_sh[c] = make_float2(wh, mem * wh);
    }
    __syncwarp();

    // packed res state: uu0={c0,c1} uu1={c2,c3} uu2={c4,c5} uu3={c6,c7}
    uint64_t uu0 = 0, uu1 = 0, uu2 = 0, uu3 = 0;
    uint64_t memm; PACK64(memm, mem, mem);

    int tq[16];
    #pragma unroll
    for (int i = 0; i < 16; i++) tq[i] = lx[i];

    ulonglong2 rA[8], rB[8];           // rA = cols 0-3, rB = cols 4-7 (packed)
    #pragma unroll
    for (int i = 0; i < 8; i++) {
        const ulonglong2* rp = (const ulonglong2*)(tm + tq[i] * NTASKS + lane * 8);
        rA[i] = rp[0];
        rB[i] = rp[1];
    }
    float tmcq[8];
    #pragma unroll
    for (int i = 0; i < 8; i++)
        tmcq[i] = __ldg(tm + tq[i] * NTASKS + tq[i + 1]);

    float g   = 0.0f;
    float P2  = 0.0f;
    float TMW = tmcq[0] * wm_sh[tq[1]].x;

    float* kout = k_buf + a * S_LEN;
    float kq[4];

    for (int sb = 0; sb < S_LEN; sb += 16) {
        #pragma unroll
        for (int u = 0; u < 16; u++) {
            const int s = sb + u;

            // ---- critical scalar chain (fma + fma + tanh) ----
            float k   = fmaf(boost, g, eff);
            float arg = fmaf(TMW, k, P2);
            g = tanhapx(arg);

            kq[u & 3] = k;
            if ((u & 3) == 3 && lane == 0)
                *(float4*)(kout + s - 3) = make_float4(kq[0], kq[1], kq[2], kq[3]);

            // ---- packed vector res update ----
            uint64_t kk; PACK64(kk, k, k);
            uint64_t p0, p1, p2, p3;
            MULX2(p0, rA[u & 7].x, kk); FMAX2(uu0, uu0, memm, p0);
            MULX2(p1, rA[u & 7].y, kk); FMAX2(uu1, uu1, memm, p1);
            MULX2(p2, rB[u & 7].x, kk); FMAX2(uu2, uu2, memm, p2);
            MULX2(p3, rB[u & 7].y, kk); FMAX2(uu3, uu3, memm, p3);

            // ---- cross-lane extract of r_s(t_{s+2}) ----
            const int cn = tq[(u + 2) & 15];
            uint64_t sA = (cn & 2) ? uu1 : uu0;
            uint64_t sB = (cn & 2) ? uu3 : uu2;
            uint64_t sv = (cn & 4) ? sB : sA;
            float lo, hi; UNPACK64(lo, hi, sv);
            float v  = (cn & 1) ? hi : lo;
            float bc = __shfl_sync(0xffffffffu, v, cn >> 3);
            const float2 wmn = wm_sh[cn];
            P2  = bc * wmn.y;
            TMW = tmcq[(u + 1) & 7] * wmn.x;

            // ---- prefetch step s+8; refill t queue ----
            const int t8 = tq[(u + 8) & 15];
            const int t9 = tq[(u + 9) & 15];
            const ulonglong2* rp = (const ulonglong2*)(tm + t8 * NTASKS + lane * 8);
            rA[u & 7] = rp[0];
            rB[u & 7] = rp[1];
            tmcq[u & 7] = __ldg(tm + t8 * NTASKS + t9);

            const int nidx = s + 16;
            tq[u] = lx[nidx < S_LEN ? nidx : (S_LEN - 1)];
        }
    }
}

// ---------------------------------------------------------------------------
// Follower: grid = 64 algos x 8 colgroups x 4 chunkblocks. Block = 128 thr.
// Each block stages tm[:, cg*32 .. cg*32+32) (32KB) + per-step (t,k) pairs
// into smem; each warp runs one 256-step chunk (128-step warm-up) over its
// 32 columns entirely from shared memory.
// ---------------------------------------------------------------------------
#define F_CHUNK 256
#define F_WARM  128
#define F_COLS  32

__global__ void __launch_bounds__(128) idl_follower(
    const int*   __restrict__ lx,
    const float* __restrict__ tm,
    const float* __restrict__ diff,
    const float* __restrict__ memA,
    float*       __restrict__ out)
{
    __shared__ float tm_sh[NTASKS * F_COLS];                 // 32 KB
    __shared__ int2  pr_sh[4][F_WARM + F_CHUNK];             // 12 KB

    const int b    = blockIdx.x;
    const int a    = b >> 5;            // /32
    const int cg   = (b >> 2) & 7;
    const int cb   = b & 3;
    const int tid  = threadIdx.x;
    const int w    = tid >> 5;
    const int lane = tid & 31;

    // stage tm column slice (coalesced 128B per warp-read)
    #pragma unroll
    for (int i = tid; i < NTASKS * F_COLS; i += 128) {
        const int r = i >> 5;
        const int c = i & 31;
        tm_sh[i] = __ldg(tm + r * NTASKS + cg * F_COLS + c);
    }

    // stage this warp's (t*32, k) pair stream
    const int q      = cb * 4 + w;          // global s-chunk 0..15
    const int s_main = q * F_CHUNK;
    const int warm_n = (q == 0) ? 0 : F_WARM;
    const int s_base = s_main - warm_n;
    const int count  = warm_n + F_CHUNK;
    const float* kptr = k_buf + a * S_LEN;
    for (int i = lane; i < count; i += 32) {
        const int s = s_base + i;
        pr_sh[w][i] = make_int2(__ldg(lx + s) * F_COLS,
                                __float_as_int(__ldg(kptr + s)));
    }
    __syncthreads();

    const int   col = cg * F_COLS + lane;
    const float mem = memA[a];
    const float wh  = 0.5f * rcpf(__ldg(diff + col));

    float r = 0.0f;

    #pragma unroll 8
    for (int i = 0; i < warm_n; i++) {
        const int2 p = pr_sh[w][i];
        r = fmaf(r, mem, tm_sh[p.x + lane] * __int_as_float(p.y));
    }

    float* op = out + (size_t)(a * NTASKS + col) * (size_t)(S_LEN + 1) + 1 + s_main;
    if (q == 0) op[-1] = 0.0f;

    #pragma unroll 8
    for (int j = 0; j < F_CHUNK; j++) {
        const int2 p = pr_sh[w][warm_n + j];
        r = fmaf(r, mem, tm_sh[p.x + lane] * __int_as_float(p.y));
        op[j] = tanhapx(r * wh);
    }
}

extern "C" void kernel_launch(void* const* d_in, const int* in_sizes, int n_in,
                              void* d_out, int out_size)
{
    (void)in_sizes; (void)n_in; (void)out_size;
    const int*   lx    = (const int*)  d_in[0];
    const float* tm    = (const float*)d_in[1];
    const float* diff  = (const float*)d_in[2];
    const float* eff   = (const float*)d_in[3];
    const float* mem   = (const float*)d_in[4];
    const float* boost = (const float*)d_in[5];
    float*       out   = (float*)d_out;

    idl_producer<<<NALGOS, 32>>>(lx, tm, diff, eff, mem, boost);
    idl_follower<<<NALGOS * 8 * 4, 128>>>(lx, tm, diff, mem, out);
}

// round 4
// speedup vs baseline: 2.2634x; 1.0798x over previous
#include <cuda_runtime.h>
#include <cstdint>

#define S_LEN   4096
#define NTASKS  256
#define NALGOS  64

// k[a][s] = eff_a + boost_a * sig_{s-1}(t_s)
__device__ __align__(16) float  k_buf[NALGOS * S_LEN];
// prep[a][s] = {T1w_s, BC_{s+1}, AC_{s+2}, TM3_s}
__device__ __align__(16) float4 prep_buf[NALGOS * S_LEN];

__device__ __forceinline__ float rcpf(float x) {
    float y; asm("rcp.approx.f32 %0, %1;" : "=f"(y) : "f"(x)); return y;
}
__device__ __forceinline__ float tanhapx(float x) {
    float y; asm("tanh.approx.f32 %0, %1;" : "=f"(y) : "f"(x)); return y;
}

#define PACK64(u, lo, hi)   asm("mov.b64 %0, {%1, %2};" : "=l"(u) : "f"(lo), "f"(hi))
#define UNPACK64(lo, hi, u) asm("mov.b64 {%0, %1}, %2;" : "=f"(lo), "=f"(hi) : "l"(u))
#define MULX2(o, a, b)      asm("mul.rn.f32x2 %0, %1, %2;" : "=l"(o) : "l"(a), "l"(b))
#define FMAX2(o, a, b, c)   asm("fma.rn.f32x2 %0, %1, %2, %3;" : "=l"(o) : "l"(a), "l"(b), "l"(c))

// ---------------------------------------------------------------------------
// Prep: per (a, s) coefficient packing for the producer's deferred chain.
//   T1w_s = tm[t_s][t_{s+1}] * wh(t_{s+1})
//   BC_{s+1} = wh(t_{s+2}) * mem * tm[t_s][t_{s+2}]
//   AC_{s+2} = wh(t_{s+3}) * mem^2
//   TM3_s = tm[t_s][t_{s+3}]
// ---------------------------------------------------------------------------
__global__ void __launch_bounds__(128) idl_prep(
    const int* __restrict__ lx, const float* __restrict__ tm,
    const float* __restrict__ diff, const float* __restrict__ memA)
{
    const int a = blockIdx.x >> 5;
    const int s = ((blockIdx.x & 31) << 7) + threadIdx.x;
    const float mem = memA[a];

    const int t0 = __ldg(lx + s);
    const int t1 = __ldg(lx + min(s + 1, S_LEN - 1));
    const int t2 = __ldg(lx + min(s + 2, S_LEN - 1));
    const int t3 = __ldg(lx + min(s + 3, S_LEN - 1));

    const float wh1 = 0.5f * rcpf(__ldg(diff + t1));
    const float wh2 = 0.5f * rcpf(__ldg(diff + t2));
    const float wh3 = 0.5f * rcpf(__ldg(diff + t3));

    float4 o;
    o.x = __ldg(tm + t0 * NTASKS + t1) * wh1;
    o.y = __ldg(tm + t0 * NTASKS + t2) * (wh2 * mem);
    o.z = wh3 * mem * mem;
    o.w = __ldg(tm + t0 * NTASKS + t3);
    prep_buf[a * S_LEN + s] = o;
}

// ---------------------------------------------------------------------------
// Producer: one warp per algo. Chain = fma+fma+tanh (24 cyc). Cross-lane
// extract operates on 3-step-old state (deferred expansion), fully off-chain.
// ---------------------------------------------------------------------------
__global__ void __launch_bounds__(32, 1) idl_producer(
    const int*   __restrict__ lx,
    const float* __restrict__ tm,
    const float* __restrict__ effA,
    const float* __restrict__ memA,
    const float* __restrict__ boostA)
{
    const int a    = blockIdx.x;
    const int lane = threadIdx.x;

    const float mem   = memA[a];
    const float eff   = effA[a];
    const float boost = boostA[a];

    uint64_t uu0 = 0, uu1 = 0, uu2 = 0, uu3 = 0;   // packed res, cols lane*8+0..7
    uint64_t memm; PACK64(memm, mem, mem);

    int tq[16];
    #pragma unroll
    for (int i = 0; i < 16; i++) tq[i] = lx[i];

    ulonglong2 rA[8], rB[8];
    #pragma unroll
    for (int i = 0; i < 8; i++) {
        const ulonglong2* rp = (const ulonglong2*)(tm + tq[i] * NTASKS + lane * 8);
        rA[i] = rp[0];
        rB[i] = rp[1];
    }
    const float4* prp = prep_buf + a * S_LEN;
    float4 PF[8];
    #pragma unroll
    for (int i = 0; i < 8; i++) PF[i] = __ldg(prp + i);

    float g = 0.0f, base = 0.0f, pb1 = 0.0f, Am = 0.0f;

    float* kout = k_buf + a * S_LEN;
    float kq[4];

    for (int sb = 0; sb < S_LEN; sb += 16) {
        #pragma unroll
        for (int u = 0; u < 16; u++) {
            const int s = sb + u;
            const float4 pf = PF[u & 7];

            // ---- critical chain ----
            float k   = fmaf(boost, g, eff);
            float arg = fmaf(k, pf.x, base);
            g = tanhapx(arg);

            kq[u & 3] = k;
            if ((u & 3) == 3 && lane == 0)
                *(float4*)(kout + s - 3) = make_float4(kq[0], kq[1], kq[2], kq[3]);

            // ---- off-chain pipeline ----
            base = fmaf(k, pf.y, pb1);            // base_{s+1}
            float inner = fmaf(k, pf.w, Am);      // inner_{s+2}
            pb1 = pf.z * inner;                   // pbase_{s+2}

            // ---- packed vector res update ----
            uint64_t kk; PACK64(kk, k, k);
            uint64_t p0, p1, p2, p3;
            MULX2(p0, rA[u & 7].x, kk); FMAX2(uu0, uu0, memm, p0);
            MULX2(p1, rA[u & 7].y, kk); FMAX2(uu1, uu1, memm, p1);
            MULX2(p2, rB[u & 7].x, kk); FMAX2(uu2, uu2, memm, p2);
            MULX2(p3, rB[u & 7].y, kk); FMAX2(uu3, uu3, memm, p3);

            // ---- extract A_{s+3} = r_s(t_{s+4}) ----
            const int cn = tq[(u + 4) & 15];
            uint64_t sA = (cn & 2) ? uu1 : uu0;
            uint64_t sB = (cn & 2) ? uu3 : uu2;
            uint64_t sv = (cn & 4) ? sB : sA;
            float lo, hi; UNPACK64(lo, hi, sv);
            float v  = (cn & 1) ? hi : lo;
            float bc = __shfl_sync(0xffffffffu, v, cn >> 3);
            Am = mem * bc;                        // mem*A_{s+3}

            // ---- prefetch step s+8 ----
            const int t8 = tq[(u + 8) & 15];
            const ulonglong2* rp = (const ulonglong2*)(tm + t8 * NTASKS + lane * 8);
            rA[u & 7] = rp[0];
            rB[u & 7] = rp[1];
            const int nidx = s + 8;
            PF[u & 7] = __ldg(prp + (nidx < S_LEN ? nidx : (S_LEN - 1)));
            const int qidx = s + 16;
            tq[u] = lx[qidx < S_LEN ? qidx : (S_LEN - 1)];
        }
    }
}

// ---------------------------------------------------------------------------
// Follower: grid = 64 algos x 8 colgroups x 4 chunkblocks, block = 128.
// tm column slice + (t,k) stream staged in smem; per-warp transpose buffer
// turns stores into contiguous 8-float runs per column (coalesced sectors).
// ---------------------------------------------------------------------------
#define F_CHUNK 256
#define F_WARM  128
#define F_COLS  32

__global__ void __launch_bounds__(128) idl_follower(
    const int*   __restrict__ lx,
    const float* __restrict__ tm,
    const float* __restrict__ diff,
    const float* __restrict__ memA,
    float*       __restrict__ out)
{
    __shared__ float    tm_sh[NTASKS * F_COLS];            // 32 KB
    __shared__ uint16_t t16_sh[4][F_WARM + F_CHUNK];       // 3 KB   (t*32)
    __shared__ float    kf_sh[4][F_WARM + F_CHUNK];        // 6 KB
    __shared__ float    sbuf[4][F_COLS][9];                // 4.5 KB

    const int b    = blockIdx.x;
    const int a    = b >> 5;
    const int cg   = (b >> 2) & 7;
    const int cb   = b & 3;
    const int tid  = threadIdx.x;
    const int w    = tid >> 5;
    const int lane = tid & 31;

    // stage tm column slice (coalesced)
    #pragma unroll
    for (int i = tid; i < NTASKS * F_COLS; i += 128)
        tm_sh[i] = __ldg(tm + (i >> 5) * NTASKS + cg * F_COLS + (i & 31));

    // stage this warp's (t, k) stream
    const int q      = cb * 4 + w;
    const int s_main = q * F_CHUNK;
    const int warm_n = (q == 0) ? 0 : F_WARM;
    const int s_base = s_main - warm_n;
    const int count  = warm_n + F_CHUNK;
    const float* kptr = k_buf + a * S_LEN;
    for (int i = lane; i < count; i += 32) {
        const int s = s_base + i;
        t16_sh[w][i] = (uint16_t)(__ldg(lx + s) * F_COLS);
        kf_sh[w][i]  = __ldg(kptr + s);
    }
    __syncthreads();

    const int   col = cg * F_COLS + lane;
    const float mem = memA[a];
    const float wh  = 0.5f * rcpf(__ldg(diff + col));

    float r = 0.0f;

    #pragma unroll 8
    for (int i = 0; i < warm_n; i++) {
        const float tv = tm_sh[(int)t16_sh[w][i] + lane];
        r = fmaf(r, mem, tv * kf_sh[w][i]);
    }

    // transposed output pointer: this lane stores column (cg*32 + lane>>3 + 4*i2)
    // at j-offset (lane&7)
    float* outp = out + (size_t)(a * NTASKS + cg * F_COLS + (lane >> 3)) * (size_t)(S_LEN + 1)
                 + 1 + s_main + (lane & 7);
    if (q == 0) {
        // zero column 0 for this block's 32 columns
        out[(size_t)(a * NTASKS + col) * (size_t)(S_LEN + 1)] = 0.0f;
    }

    #pragma unroll 4
    for (int jb = 0; jb < F_CHUNK / 8; jb++) {
        #pragma unroll
        for (int j = 0; j < 8; j++) {
            const int i = warm_n + jb * 8 + j;
            const float tv = tm_sh[(int)t16_sh[w][i] + lane];
            r = fmaf(r, mem, tv * kf_sh[w][i]);
            sbuf[w][lane][j] = tanhapx(r * wh);
        }
        __syncwarp();
        #pragma unroll
        for (int i2 = 0; i2 < 8; i2++) {
            const float v = sbuf[w][i2 * 4 + (lane >> 3)][lane & 7];
            outp[(size_t)(i2 * 4) * (size_t)(S_LEN + 1) + jb * 8] = v;
        }
        __syncwarp();
    }
}

extern "C" void kernel_launch(void* const* d_in, const int* in_sizes, int n_in,
                              void* d_out, int out_size)
{
    (void)in_sizes; (void)n_in; (void)out_size;
    const int*   lx    = (const int*)  d_in[0];
    const float* tm    = (const float*)d_in[1];
    const float* diff  = (const float*)d_in[2];
    const float* eff   = (const float*)d_in[3];
    const float* mem   = (const float*)d_in[4];
    const float* boost = (const float*)d_in[5];
    float*       out   = (float*)d_out;

    idl_prep<<<NALGOS * 32, 128>>>(lx, tm, diff, mem);
    idl_producer<<<NALGOS, 32>>>(lx, tm, eff, mem, boost);
    idl_follower<<<NALGOS * 8 * 4, 128>>>(lx, tm, diff, mem, out);
}

// round 5
// speedup vs baseline: 2.7456x; 1.2131x over previous
#include <cuda_runtime.h>
#include <cstdint>

#define S_LEN   4096
#define NTASKS  256
#define NALGOS  64

// k[a][s] = eff_a + boost_a * sig_{s-1}(t_s)
__device__ __align__(16) float  k_buf[NALGOS * S_LEN];
// prep[a][s] = {T1w_s, BC_{s+1}, AC_{s+2}, TM3_s}
__device__ __align__(16) float4 prep_buf[NALGOS * S_LEN];
// producer progress (steps completed), reset by prep each run
__device__ int g_prog[NALGOS];

__device__ __forceinline__ float rcpf(float x) {
    float y; asm("rcp.approx.f32 %0, %1;" : "=f"(y) : "f"(x)); return y;
}
__device__ __forceinline__ float tanhapx(float x) {
    float y; asm("tanh.approx.f32 %0, %1;" : "=f"(y) : "f"(x)); return y;
}
__device__ __forceinline__ float ldcg(const float* p) {
    float v; asm volatile("ld.global.cg.f32 %0, [%1];" : "=f"(v) : "l"(p)); return v;
}

#define PACK64(u, lo, hi)   asm("mov.b64 %0, {%1, %2};" : "=l"(u) : "f"(lo), "f"(hi))
#define UNPACK64(lo, hi, u) asm("mov.b64 {%0, %1}, %2;" : "=f"(lo), "=f"(hi) : "l"(u))
#define MULX2(o, a, b)      asm("mul.rn.f32x2 %0, %1, %2;" : "=l"(o) : "l"(a), "l"(b))
#define FMAX2(o, a, b, c)   asm("fma.rn.f32x2 %0, %1, %2, %3;" : "=l"(o) : "l"(a), "l"(b), "l"(c))

// ---------------------------------------------------------------------------
// Prep: coefficient packing for the producer's deferred (D=3) chain; also
// resets the progress flags for this run.
// ---------------------------------------------------------------------------
__global__ void __launch_bounds__(128) idl_prep(
    const int* __restrict__ lx, const float* __restrict__ tm,
    const float* __restrict__ diff, const float* __restrict__ memA)
{
    if (blockIdx.x == 0 && threadIdx.x < NALGOS)
        g_prog[threadIdx.x] = 0;

    const int a = blockIdx.x >> 5;
    const int s = ((blockIdx.x & 31) << 7) + threadIdx.x;
    const float mem = memA[a];

    const int t0 = __ldg(lx + s);
    const int t1 = __ldg(lx + min(s + 1, S_LEN - 1));
    const int t2 = __ldg(lx + min(s + 2, S_LEN - 1));
    const int t3 = __ldg(lx + min(s + 3, S_LEN - 1));

    const float wh1 = 0.5f * rcpf(__ldg(diff + t1));
    const float wh2 = 0.5f * rcpf(__ldg(diff + t2));
    const float wh3 = 0.5f * rcpf(__ldg(diff + t3));

    float4 o;
    o.x = __ldg(tm + t0 * NTASKS + t1) * wh1;
    o.y = __ldg(tm + t0 * NTASKS + t2) * (wh2 * mem);
    o.z = wh3 * mem * mem;
    o.w = __ldg(tm + t0 * NTASKS + t3);
    prep_buf[a * S_LEN + s] = o;
}

#define F_CHUNK 256
#define F_WARM  128
#define F_COLS  32
#define PROD_BLOCKS NALGOS

// ---------------------------------------------------------------------------
// Fused kernel. Blocks [0,64): producer (1 warp). Blocks [64, 64+2048):
// follower, overlapped with producer via acquire/release progress flags.
// ---------------------------------------------------------------------------
__global__ void __launch_bounds__(128, 4) idl_fused(
    const int*   __restrict__ lx,
    const float* __restrict__ tm,
    const float* __restrict__ diff,
    const float* __restrict__ effA,
    const float* __restrict__ memA,
    const float* __restrict__ boostA,
    float*       __restrict__ out)
{
    __shared__ float    tm_sh[NTASKS * F_COLS];            // 32 KB
    __shared__ uint16_t t16_sh[4][F_WARM + F_CHUNK];       // 3 KB
    __shared__ float    kf_sh[4][F_WARM + F_CHUNK];        // 6 KB
    __shared__ float    sbuf[4][F_COLS][17];               // 8.5 KB

    if (blockIdx.x < PROD_BLOCKS) {
        // ================= PRODUCER =================
        if (threadIdx.x >= 32) return;
        const int a    = blockIdx.x;
        const int lane = threadIdx.x;

        const float mem   = memA[a];
        const float eff   = effA[a];
        const float boost = boostA[a];

        uint64_t uu0 = 0, uu1 = 0, uu2 = 0, uu3 = 0;
        uint64_t memm; PACK64(memm, mem, mem);

        int tq[16];
        #pragma unroll
        for (int i = 0; i < 16; i++) tq[i] = lx[i];

        ulonglong2 rA[4], rB[4];                 // row ring depth 4
        #pragma unroll
        for (int i = 0; i < 4; i++) {
            const ulonglong2* rp = (const ulonglong2*)(tm + tq[i] * NTASKS + lane * 8);
            rA[i] = rp[0];
            rB[i] = rp[1];
        }
        const float4* prp = prep_buf + a * S_LEN;
        float4 PF[8];
        #pragma unroll
        for (int i = 0; i < 8; i++) PF[i] = __ldg(prp + i);

        float g = 0.0f, base = 0.0f, pb1 = 0.0f, Am = 0.0f;
        float* kout = k_buf + a * S_LEN;
        float kq[4];

        for (int sb = 0; sb < S_LEN; sb += 16) {
            #pragma unroll
            for (int u = 0; u < 16; u++) {
                const int s = sb + u;
                const float4 pf = PF[u & 7];

                // critical chain
                float k   = fmaf(boost, g, eff);
                float arg = fmaf(k, pf.x, base);
                g = tanhapx(arg);

                kq[u & 3] = k;
                if ((u & 3) == 3 && lane == 0) {
                    *(float4*)(kout + s - 3) = make_float4(kq[0], kq[1], kq[2], kq[3]);
                    if ((s & 255) == 255) {
                        int pv = s + 1;
                        asm volatile("st.global.release.gpu.s32 [%0], %1;"
                                     :: "l"(g_prog + a), "r"(pv) : "memory");
                    }
                }

                // off-chain pipeline
                base = fmaf(k, pf.y, pb1);
                float inner = fmaf(k, pf.w, Am);
                pb1 = pf.z * inner;

                // packed vector res update (cols lane*8..+7)
                uint64_t kk; PACK64(kk, k, k);
                uint64_t p0, p1, p2, p3;
                MULX2(p0, rA[u & 3].x, kk); FMAX2(uu0, uu0, memm, p0);
                MULX2(p1, rA[u & 3].y, kk); FMAX2(uu1, uu1, memm, p1);
                MULX2(p2, rB[u & 3].x, kk); FMAX2(uu2, uu2, memm, p2);
                MULX2(p3, rB[u & 3].y, kk); FMAX2(uu3, uu3, memm, p3);

                // extract A = res_s(t_{s+4})
                const int cn = tq[(u + 4) & 15];
                uint64_t sA = (cn & 2) ? uu1 : uu0;
                uint64_t sB = (cn & 2) ? uu3 : uu2;
                uint64_t sv = (cn & 4) ? sB : sA;
                float lo, hi; UNPACK64(lo, hi, sv);
                float v  = (cn & 1) ? hi : lo;
                float bc = __shfl_sync(0xffffffffu, v, cn >> 3);
                Am = mem * bc;

                // refills: row for s+4, PF for s+8, tq for s+16
                const ulonglong2* rp = (const ulonglong2*)(tm + cn * NTASKS + lane * 8);
                rA[u & 3] = rp[0];
                rB[u & 3] = rp[1];
                const int nidx = s + 8;
                PF[u & 7] = __ldg(prp + (nidx < S_LEN ? nidx : (S_LEN - 1)));
                const int qidx = s + 16;
                tq[u] = lx[qidx < S_LEN ? qidx : (S_LEN - 1)];
            }
        }
        return;
    }

    // ================= FOLLOWER =================
    const int b    = blockIdx.x - PROD_BLOCKS;
    const int a    = b >> 5;
    const int cg   = (b >> 2) & 7;
    const int cb   = b & 3;
    const int tid  = threadIdx.x;
    const int w    = tid >> 5;
    const int lane = tid & 31;

    // stage tm column slice (input, immutable)
    #pragma unroll
    for (int i = tid; i < NTASKS * F_COLS; i += 128)
        tm_sh[i] = __ldg(tm + (i >> 5) * NTASKS + cg * F_COLS + (i & 31));
    __syncthreads();

    const int q      = cb * 4 + w;
    const int s_main = q * F_CHUNK;
    const int warm_n = (q == 0) ? 0 : F_WARM;
    const int s_base = s_main - warm_n;
    const int count  = warm_n + F_CHUNK;

    // wait for producer progress past this warp's range
    if (lane == 0) {
        const int need = s_main + F_CHUNK;
        int p;
        for (;;) {
            asm volatile("ld.global.acquire.gpu.s32 %0, [%1];"
                         : "=r"(p) : "l"(g_prog + a) : "memory");
            if (p >= need) break;
            __nanosleep(200);
        }
    }
    __syncwarp();

    // stage this warp's (t, k) stream (k via L2-coherent loads)
    const float* kptr = k_buf + a * S_LEN;
    for (int i = lane; i < count; i += 32) {
        const int s = s_base + i;
        t16_sh[w][i] = (uint16_t)(__ldg(lx + s) * F_COLS);
        kf_sh[w][i]  = ldcg(kptr + s);
    }
    __syncwarp();

    const int   col = cg * F_COLS + lane;
    const float mem = memA[a];
    const float wh  = 0.5f * rcpf(__ldg(diff + col));

    float r = 0.0f;

    #pragma unroll 8
    for (int i = 0; i < warm_n; i++) {
        const float tv = tm_sh[(int)t16_sh[w][i] + lane];
        r = fmaf(r, mem, tv * kf_sh[w][i]);
    }

    // transposed store pointer: lane stores column (cg*32 + (lane>>4) + 2*i2)
    // at j-offset (lane&15)
    float* outp = out + (size_t)(a * NTASKS + cg * F_COLS + (lane >> 4)) * (size_t)(S_LEN + 1)
                 + 1 + s_main + (lane & 15);
    if (q == 0)
        out[(size_t)(a * NTASKS + col) * (size_t)(S_LEN + 1)] = 0.0f;

    #pragma unroll 2
    for (int jb = 0; jb < F_CHUNK / 16; jb++) {
        #pragma unroll
        for (int j = 0; j < 16; j++) {
            const int i = warm_n + jb * 16 + j;
            const float tv = tm_sh[(int)t16_sh[w][i] + lane];
            r = fmaf(r, mem, tv * kf_sh[w][i]);
            sbuf[w][lane][j] = tanhapx(r * wh);
        }
        __syncwarp();
        #pragma unroll
        for (int i2 = 0; i2 < 16; i2++) {
            const float v = sbuf[w][i2 * 2 + (lane >> 4)][lane & 15];
            outp[(size_t)(i2 * 2) * (size_t)(S_LEN + 1) + jb * 16] = v;
        }
        __syncwarp();
    }
}

extern "C" void kernel_launch(void* const* d_in, const int* in_sizes, int n_in,
                              void* d_out, int out_size)
{
    (void)in_sizes; (void)n_in; (void)out_size;
    const int*   lx    = (const int*)  d_in[0];
    const float* tm    = (const float*)d_in[1];
    const float* diff  = (const float*)d_in[2];
    const float* eff   = (const float*)d_in[3];
    const float* mem   = (const float*)d_in[4];
    const float* boost = (const float*)d_in[5];
    float*       out   = (float*)d_out;

    idl_prep<<<NALGOS * 32, 128>>>(lx, tm, diff, mem);
    idl_fused<<<PROD_BLOCKS + NALGOS * 8 * 4, 128>>>(lx, tm, diff, eff, mem, boost, out);
}

// round 6
// speedup vs baseline: 5.4333x; 1.9789x over previous
#include <cuda_runtime.h>
#include <cstdint>

#define S_LEN   4096
#define NTASKS  256
#define NALGOS  64
#define WARM    192
#define CHUNK   256

// prep[a][s] = {T1w_s, BC_{s+1}, AC_{s+2}, TM3_s} for the D=3 deferred chain
__device__ __align__(16) float4 prep_buf[NALGOS * S_LEN];

__device__ __forceinline__ float rcpf(float x) {
    float y; asm("rcp.approx.f32 %0, %1;" : "=f"(y) : "f"(x)); return y;
}
__device__ __forceinline__ float tanhapx(float x) {
    float y; asm("tanh.approx.f32 %0, %1;" : "=f"(y) : "f"(x)); return y;
}

#define PACK64(u, lo, hi)   asm("mov.b64 %0, {%1, %2};" : "=l"(u) : "f"(lo), "f"(hi))
#define UNPACK64(lo, hi, u) asm("mov.b64 {%0, %1}, %2;" : "=f"(lo), "=f"(hi) : "l"(u))
#define MULX2(o, a, b)      asm("mul.rn.f32x2 %0, %1, %2;" : "=l"(o) : "l"(a), "l"(b))
#define FMAX2(o, a, b, c)   asm("fma.rn.f32x2 %0, %1, %2, %3;" : "=l"(o) : "l"(a), "l"(b), "l"(c))
#define LDG64(v, p) asm("ld.global.nc.b64 %0, [%1];" : "=l"(v) : "l"(p))

// ---------------------------------------------------------------------------
// Prep: coefficient packing for the deferred (D=3) chain.
// ---------------------------------------------------------------------------
__global__ void __launch_bounds__(128) idl_prep(
    const int* __restrict__ lx, const float* __restrict__ tm,
    const float* __restrict__ diff, const float* __restrict__ memA)
{
    const int a = blockIdx.x >> 5;
    const int s = ((blockIdx.x & 31) << 7) + threadIdx.x;
    const float mem = memA[a];

    const int t0 = __ldg(lx + s);
    const int t1 = __ldg(lx + min(s + 1, S_LEN - 1));
    const int t2 = __ldg(lx + min(s + 2, S_LEN - 1));
    const int t3 = __ldg(lx + min(s + 3, S_LEN - 1));

    const float wh1 = 0.5f * rcpf(__ldg(diff + t1));
    const float wh2 = 0.5f * rcpf(__ldg(diff + t2));
    const float wh3 = 0.5f * rcpf(__ldg(diff + t3));

    float4 o;
    o.x = __ldg(tm + t0 * NTASKS + t1) * wh1;
    o.y = __ldg(tm + t0 * NTASKS + t2) * (wh2 * mem);
    o.z = wh3 * mem * mem;
    o.w = __ldg(tm + t0 * NTASKS + t3);
    prep_buf[a * S_LEN + s] = o;
}

// ---------------------------------------------------------------------------
// Main: 1024 blocks = 64 algos x 16 chunks, fully independent.
// Phase 1 (warp 0): k-chain for [s0-WARM, s0+CHUNK) from zero state -> smem.
// Phase 2 (4 warps): per-lane 2-column res recurrence + tanh + transposed
// coalesced stores.
// ---------------------------------------------------------------------------
__global__ void __launch_bounds__(128) idl_main(
    const int*   __restrict__ lx,
    const float* __restrict__ tm,
    const float* __restrict__ diff,
    const float* __restrict__ effA,
    const float* __restrict__ memA,
    const float* __restrict__ boostA,
    float*       __restrict__ out)
{
    __shared__ float kf_sh[WARM + CHUNK];
    __shared__ __align__(16) float sbuf[4][16][66];

    const int b    = blockIdx.x;
    const int a    = b >> 4;
    const int q    = b & 15;
    const int tid  = threadIdx.x;
    const int w    = tid >> 5;
    const int lane = tid & 31;

    const int warm_n  = q ? WARM : 0;
    const int s0      = q * CHUNK;
    const int s_base  = s0 - warm_n;
    const int total_n = warm_n + CHUNK;

    const float mem   = memA[a];
    const float eff   = effA[a];
    const float boost = boostA[a];

    if (w == 0) {
        // ================= PHASE 1: k-chain =================
        uint64_t uu0 = 0, uu1 = 0, uu2 = 0, uu3 = 0;   // res cols lane*8+0..7
        uint64_t memm; PACK64(memm, mem, mem);

        ulonglong2 rA[4], rB[4];
        #pragma unroll
        for (int i = 0; i < 4; i++) {
            const int t = __ldg(lx + min(s_base + i, S_LEN - 1));
            const ulonglong2* rp = (const ulonglong2*)(tm + t * NTASKS + lane * 8);
            rA[i] = rp[0];
            rB[i] = rp[1];
        }
        const float4* prp = prep_buf + a * S_LEN;
        float4 PF[8];
        #pragma unroll
        for (int i = 0; i < 8; i++)
            PF[i] = __ldg(prp + min(s_base + i, S_LEN - 1));

        float g = 0.0f, base = 0.0f, pb1 = 0.0f, Am = 0.0f;

        for (int ib = 0; ib < total_n; ib += 16) {
            #pragma unroll
            for (int u = 0; u < 16; u++) {
                const int i = ib + u;
                const int s = s_base + i;
                const float4 pf = PF[u & 7];

                // critical chain
                float k   = fmaf(boost, g, eff);
                float arg = fmaf(k, pf.x, base);
                g = tanhapx(arg);
                if (lane == 0) kf_sh[i] = k;

                // off-chain D=3 pipeline
                base = fmaf(k, pf.y, pb1);
                float inner = fmaf(k, pf.w, Am);
                pb1 = pf.z * inner;

                // packed res update
                uint64_t kk; PACK64(kk, k, k);
                uint64_t p0, p1, p2, p3;
                MULX2(p0, rA[u & 3].x, kk); FMAX2(uu0, uu0, memm, p0);
                MULX2(p1, rA[u & 3].y, kk); FMAX2(uu1, uu1, memm, p1);
                MULX2(p2, rB[u & 3].x, kk); FMAX2(uu2, uu2, memm, p2);
                MULX2(p3, rB[u & 3].y, kk); FMAX2(uu3, uu3, memm, p3);

                // extract res_s(t_{s+4})
                const int cn = __ldg(lx + min(s + 4, S_LEN - 1));
                uint64_t sA = (cn & 2) ? uu1 : uu0;
                uint64_t sB = (cn & 2) ? uu3 : uu2;
                uint64_t sv = (cn & 4) ? sB : sA;
                float lo, hi; UNPACK64(lo, hi, sv);
                float v  = (cn & 1) ? hi : lo;
                float bc = __shfl_sync(0xffffffffu, v, cn >> 3);
                Am = mem * bc;

                // refill: row for step i+4 (row cn), PF for step i+8
                const ulonglong2* rp = (const ulonglong2*)(tm + cn * NTASKS + lane * 8);
                rA[u & 3] = rp[0];
                rB[u & 3] = rp[1];
                PF[u & 7] = __ldg(prp + min(s + 8, S_LEN - 1));
            }
        }
    }
    __syncthreads();

    // ================= PHASE 2: columns =================
    const int c0 = w * 64 + 2 * lane;               // cols c0, c0+1
    const float wh0 = 0.5f * rcpf(__ldg(diff + c0));
    const float wh1 = 0.5f * rcpf(__ldg(diff + c0 + 1));

    uint64_t rr = 0;
    uint64_t memm2; PACK64(memm2, mem, mem);

    // warm-up (warm_n is a multiple of 16; no sigmoid, no store)
    for (int ib = 0; ib < warm_n; ib += 16) {
        #pragma unroll
        for (int j = 0; j < 16; j++) {
            const int s = s_base + ib + j;
            const int t = __ldg(lx + s);
            uint64_t tv; LDG64(tv, (const void*)(tm + t * NTASKS + c0));
            const float kv = kf_sh[ib + j];
            uint64_t kk; PACK64(kk, kv, kv);
            uint64_t pr; MULX2(pr, tv, kk);
            FMAX2(rr, rr, memm2, pr);
        }
    }

    // main region: 16 tiles of 16 steps, transposed coalesced stores
    #pragma unroll 1
    for (int tile = 0; tile < CHUNK / 16; tile++) {
        #pragma unroll
        for (int j = 0; j < 16; j++) {
            const int idx = warm_n + tile * 16 + j;
            const int s   = s_base + idx;
            const int t   = __ldg(lx + s);
            uint64_t tv; LDG64(tv, (const void*)(tm + t * NTASKS + c0));
            const float kv = kf_sh[idx];
            uint64_t kk; PACK64(kk, kv, kv);
            uint64_t pr; MULX2(pr, tv, kk);
            FMAX2(rr, rr, memm2, pr);
            float lo, hi; UNPACK64(lo, hi, rr);
            float2 pair = make_float2(tanhapx(lo * wh0), tanhapx(hi * wh1));
            *(float2*)&sbuf[w][j][2 * lane] = pair;
        }
        __syncwarp();
        #pragma unroll
        for (int i2 = 0; i2 < 32; i2++) {
            const int cl = 2 * i2 + (lane >> 4);    // local col 0..63
            const int j  = lane & 15;
            const float v = sbuf[w][j][cl];
            out[(size_t)(a * NTASKS + w * 64 + cl) * (size_t)(S_LEN + 1)
                + 1 + s0 + tile * 16 + j] = v;
        }
        __syncwarp();
    }

    // zero output column 0 (once per algo, by the q==0 block)
    if (q == 0) {
        for (int c = tid; c < NTASKS; c += 128)
            out[(size_t)(a * NTASKS + c) * (size_t)(S_LEN + 1)] = 0.0f;
    }
}

extern "C" void kernel_launch(void* const* d_in, const int* in_sizes, int n_in,
                              void* d_out, int out_size)
{
    (void)in_sizes; (void)n_in; (void)out_size;
    const int*   lx    = (const int*)  d_in[0];
    const float* tm    = (const float*)d_in[1];
    const float* diff  = (const float*)d_in[2];
    const float* eff   = (const float*)d_in[3];
    const float* mem   = (const float*)d_in[4];
    const float* boost = (const float*)d_in[5];
    float*       out   = (float*)d_out;

    idl_prep<<<NALGOS * 32, 128>>>(lx, tm, diff, mem);
    idl_main<<<NALGOS * 16, 128>>>(lx, tm, diff, eff, mem, boost, out);
}